// round 2
// baseline (speedup 1.0000x reference)
#include <cuda_runtime.h>
#include <math.h>

#define SS 2048
#define HH 32
#define KVHN 8
#define DD 128
#define BM 64
#define BN 64
#define WIN 1024
#define SCALE_F 0.08838834764831845f

// Pre-RoPE'd K (reused across 4 heads per KV head)
__device__ float g_kr[SS * KVHN * DD];

// ---------------------------------------------------------------------------
// Kernel 1: RoPE on K -> g_kr
// One thread per (s, kv, dim-pair i in [0,64))
// ---------------------------------------------------------------------------
__global__ void rope_k_kernel(const float* __restrict__ k, const int* __restrict__ pos) {
    int idx = blockIdx.x * blockDim.x + threadIdx.x;
    int total = SS * KVHN * 64;
    if (idx >= total) return;
    int i = idx & 63;          // rotational pair index
    int skv = idx >> 6;        // s*KVHN + kv
    int s = skv >> 3;
    // inv_freq[i] = 10000^(-i/64) = 2^(-i * log2(10000)/64)
    float inv = exp2f(-(float)i * (13.287712379549449f / 64.f));
    float ang = (float)pos[s] * inv;
    float sn, cs;
    sincosf(ang, &sn, &cs);
    const float* kp = k + (size_t)skv * DD;
    float x1 = kp[i];
    float x2 = kp[i + 64];
    float* op = g_kr + (size_t)skv * DD;
    op[i]      = x1 * cs - x2 * sn;
    op[i + 64] = x2 * cs + x1 * sn;
}

// ---------------------------------------------------------------------------
// Kernel 2: flash attention, fp32 scalar.
// Grid: (SS/BM, HH). Block: 256 threads.
// Thread layout: ql = tid>>2 (query within tile), g = tid&3 (dim-quarter).
// Each thread holds 32 dims of one query (RoPE'd, pre-scaled) and 32 dims of
// the output accumulator. Dots completed via quad butterfly shfl; scores go
// through padded smem so loops can be partially unrolled without spills.
// ---------------------------------------------------------------------------
extern __shared__ float smem_dyn[];

__global__ __launch_bounds__(256, 1) void attn_kernel(
    const float* __restrict__ q,
    const float* __restrict__ v,
    const int* __restrict__ pos,
    const float* __restrict__ sinks,
    float* __restrict__ out)
{
    float* ksh = smem_dyn;                    // BN * DD
    float* vsh = smem_dyn + BN * DD;          // BN * DD
    float* psh = smem_dyn + 2 * BN * DD;      // BM * 68 (padded score rows)
    int*   pksh = (int*)(smem_dyn + 2 * BN * DD + BM * 68); // BN

    int qt = blockIdx.x;
    int h  = blockIdx.y;
    int q0 = qt * BM;
    int kvh = h >> 2;                         // group = H/KV = 4
    int tid = threadIdx.x;
    int lane = tid & 31;
    int ql = tid >> 2;
    int g  = tid & 3;
    int qg = q0 + ql;
    int pq = pos[qg];
    int d0 = g * 32;

    // Load Q row slice, apply RoPE, fold in SCALE
    float qf[32];
    {
        const float* qrow = q + ((size_t)qg * HH + h) * DD;
        #pragma unroll
        for (int i = 0; i < 32; i++) {
            int d = d0 + i;
            int r = d & 63;
            float inv = exp2f(-(float)r * (13.287712379549449f / 64.f));
            float ang = (float)pq * inv;
            float sn, cs;
            sincosf(ang, &sn, &cs);
            float x1 = qrow[r];
            float x2 = qrow[r + 64];
            qf[i] = SCALE_F * ((d < 64) ? (x1 * cs - x2 * sn) : (x2 * cs + x1 * sn));
        }
    }

    // Online softmax state: init with sink => denom gets exp(sink - m_final)
    float m = sinks[h];
    float l = 1.0f;
    float o[32];
    #pragma unroll
    for (int i = 0; i < 32; i++) o[i] = 0.f;

    int kstart = q0 - (WIN - 1);
    if (kstart < 0) kstart = 0;
    kstart &= ~(BN - 1);            // tile-align down; extra rows get masked
    int kend = q0 + BM;             // exclusive

    for (int kb = kstart; kb < kend; kb += BN) {
        __syncthreads();
        // Cooperative tile load: 64 rows x 128 floats for K and V = 2048 float4 each
        #pragma unroll
        for (int j = 0; j < 8; j++) {
            int f = tid + 256 * j;
            int row = f >> 5;
            int c4 = f & 31;
            int kg = kb + row;
            float4 kv4 = make_float4(0.f, 0.f, 0.f, 0.f);
            float4 vv4 = make_float4(0.f, 0.f, 0.f, 0.f);
            if (kg < SS) {
                kv4 = ((const float4*)(g_kr + ((size_t)kg * KVHN + kvh) * DD))[c4];
                vv4 = ((const float4*)(v    + ((size_t)kg * KVHN + kvh) * DD))[c4];
            }
            ((float4*)ksh)[row * 32 + c4] = kv4;
            ((float4*)vsh)[row * 32 + c4] = vv4;
        }
        if (tid < BN) {
            int kg = kb + tid;
            pksh[tid] = (kg < SS) ? pos[kg] : 0x7fffffff;
        }
        __syncthreads();

        // ---- QK: scores for this tile ----
        float tmax = -1e30f;
        #pragma unroll 8
        for (int kk = 0; kk < BN; kk++) {
            const float4* kp = (const float4*)(ksh + kk * DD + d0);
            float acc = 0.f;
            #pragma unroll
            for (int i = 0; i < 8; i++) {
                float4 k4 = kp[i];
                acc += qf[4*i+0] * k4.x + qf[4*i+1] * k4.y
                     + qf[4*i+2] * k4.z + qf[4*i+3] * k4.w;
            }
            acc += __shfl_xor_sync(0xffffffffu, acc, 1);
            acc += __shfl_xor_sync(0xffffffffu, acc, 2);
            int pk = pksh[kk];
            bool okm = (pk <= pq) && (pq - pk < WIN);
            float s = okm ? acc : -1e30f;
            tmax = fmaxf(tmax, s);
            if (g == 0) psh[ql * 68 + kk] = s;   // padded row: conflict-free
        }
        __syncwarp();

        float mnew = fmaxf(m, tmax);
        float scale = __expf(m - mnew);
        m = mnew;
        #pragma unroll
        for (int i = 0; i < 32; i++) o[i] *= scale;

        // ---- PV: accumulate ----
        float lsum = 0.f;
        #pragma unroll 8
        for (int kk = 0; kk < BN; kk++) {
            float s = psh[ql * 68 + kk];
            float p = __expf(s - mnew);
            lsum += p;
            const float4* vp = (const float4*)(vsh + kk * DD + d0);
            #pragma unroll
            for (int i = 0; i < 8; i++) {
                float4 v4 = vp[i];
                o[4*i+0] += p * v4.x;
                o[4*i+1] += p * v4.y;
                o[4*i+2] += p * v4.z;
                o[4*i+3] += p * v4.w;
            }
        }
        l = l * scale + lsum;
    }

    float inv_l = 1.0f / l;
    float* op = out + ((size_t)qg * HH + h) * DD + d0;
    #pragma unroll
    for (int i = 0; i < 8; i++) {
        float4 r;
        r.x = o[4*i+0] * inv_l;
        r.y = o[4*i+1] * inv_l;
        r.z = o[4*i+2] * inv_l;
        r.w = o[4*i+3] * inv_l;
        ((float4*)op)[i] = r;
    }
}

// ---------------------------------------------------------------------------
extern "C" void kernel_launch(void* const* d_in, const int* in_sizes, int n_in,
                              void* d_out, int out_size) {
    (void)in_sizes; (void)n_in; (void)out_size;
    const float* q     = (const float*)d_in[0];
    const float* k     = (const float*)d_in[1];
    const float* v     = (const float*)d_in[2];
    const int*   pos   = (const int*)d_in[3];
    const float* sinks = (const float*)d_in[4];
    float* out = (float*)d_out;

    rope_k_kernel<<<(SS * KVHN * 64 + 255) / 256, 256>>>(k, pos);

    size_t smem = (size_t)(2 * BN * DD + BM * 68) * sizeof(float) + BN * sizeof(int);
    cudaFuncSetAttribute(attn_kernel, cudaFuncAttributeMaxDynamicSharedMemorySize, (int)smem);
    dim3 grid(SS / BM, HH);
    attn_kernel<<<grid, 256, smem>>>(q, v, pos, sinks, out);
}

// round 3
// speedup vs baseline: 6.2632x; 6.2632x over previous
#include <cuda_runtime.h>
#include <math.h>

#define SS 2048
#define HH 32
#define KVHN 8
#define DD 128
#define BM 64
#define BN 64
#define WIN 1024
#define SCALE_F 0.08838834764831845f
#define L2K 13.287712379549449f   // log2(10000)

#define KT_STR 68                 // padded d-major tile stride (x4 aligned)
#define P_STR 68

// RoPE'd K, transposed to [kv][d][s] so attention tile loads are coalesced
// and arrive in smem already d-major. 8 MB — fits L2.
__device__ float g_kt[(size_t)KVHN * DD * SS];

// ---------------------------------------------------------------------------
// Kernel 1: RoPE K -> g_kt (transposed). Lanes map to s (coalesced writes).
// ---------------------------------------------------------------------------
__global__ void rope_k_kernel(const float* __restrict__ k, const int* __restrict__ pos) {
    int idx = blockIdx.x * blockDim.x + threadIdx.x;   // KVHN*64*SS threads
    int s  = idx & (SS - 1);
    int i  = (idx >> 11) & 63;
    int kv = idx >> 17;
    float inv = exp2f(-(float)i * (L2K / 64.f));
    float sn, cs;
    sincosf((float)pos[s] * inv, &sn, &cs);
    const float* kp = k + ((size_t)s * KVHN + kv) * DD;
    float x1 = kp[i];
    float x2 = kp[i + 64];
    g_kt[((size_t)kv * DD + i)      * SS + s] = x1 * cs - x2 * sn;
    g_kt[((size_t)kv * DD + i + 64) * SS + s] = x2 * cs + x1 * sn;
}

// ---------------------------------------------------------------------------
// Kernel 2: flash attention, register-tiled fp32.
// Grid (SS/BM, HH), 256 threads.
// QK: thread (tq,tk) in 16x16 grid computes 4q x 4k. PV: 4q x 8d.
// Softmax bookkeeping (m,l,scale) per query kept in smem; no shfl in hot loops.
// ---------------------------------------------------------------------------
extern __shared__ float sm[];

__global__ __launch_bounds__(256, 1) void attn_kernel(
    const float* __restrict__ q,
    const float* __restrict__ v,
    const int* __restrict__ pos,
    const float* __restrict__ sinks,
    float* __restrict__ out)
{
    float* Qt = sm;                       // DD x KT_STR (d-major, scaled+RoPE'd Q)
    float* Kt = Qt + DD * KT_STR;         // DD x KT_STR (d-major K tile)
    float* Vs = Kt + DD * KT_STR;         // BN x DD     (row-major V tile)
    float* Ps = Vs + BN * DD;             // BM x P_STR  (scores -> probs)
    float* Ms = Ps + BM * P_STR;          // BM running max
    float* Ls = Ms + BM;                  // BM running denom
    float* Sc = Ls + BM;                  // BM per-tile rescale factor

    int qt = blockIdx.x, h = blockIdx.y;
    int q0 = qt * BM;
    int kvh = h >> 2;                     // group = 4
    int tid = threadIdx.x;
    int tq = tid >> 4, tk = tid & 15;     // GEMM phases
    int ql = tid >> 2, g = tid & 3;       // prologue / softmax crew

    // ---- Prologue: RoPE Q (scaled) into d-major Qt; init softmax state ----
    {
        int qg = q0 + ql;
        int pq = pos[qg];
        const float* qrow = q + ((size_t)qg * HH + h) * DD;
        int d0 = g * 32;
        #pragma unroll
        for (int ii = 0; ii < 32; ii++) {
            int d = d0 + ii;
            int r = d & 63;
            float inv = exp2f(-(float)r * (L2K / 64.f));
            float sn, cs;
            sincosf((float)pq * inv, &sn, &cs);
            float x1 = qrow[r], x2 = qrow[r + 64];
            float val = (d < 64) ? (x1 * cs - x2 * sn) : (x2 * cs + x1 * sn);
            Qt[d * KT_STR + ql] = SCALE_F * val;
        }
        if (tid < BM) { Ms[tid] = sinks[h]; Ls[tid] = 1.0f; }
    }

    int pq4[4];
    #pragma unroll
    for (int i = 0; i < 4; i++) pq4[i] = pos[q0 + tq * 4 + i];

    float o[32];
    #pragma unroll
    for (int i = 0; i < 32; i++) o[i] = 0.f;

    int kstart = q0 - (WIN - 1);
    if (kstart < 0) kstart = 0;
    kstart &= ~(BN - 1);
    int kend = q0 + BM;

    for (int kb = kstart; kb < kend; kb += BN) {
        __syncthreads();   // prev PV done; Qt ready (first iter)
        // ---- Cooperative tile load: Kt (already transposed in gmem), Vs ----
        #pragma unroll
        for (int j = 0; j < 8; j++) {
            int f = tid + 256 * j;
            {   // K: 128 d-rows x 16 float4
                int d = f >> 4, c4 = f & 15;
                float4 k4 = *(const float4*)(g_kt + ((size_t)kvh * DD + d) * SS + kb + c4 * 4);
                *(float4*)&Kt[d * KT_STR + c4 * 4] = k4;
            }
            {   // V: 64 rows x 32 float4
                int row = f >> 5, c4 = f & 31;
                float4 v4 = *(const float4*)(v + ((size_t)(kb + row) * KVHN + kvh) * DD + c4 * 4);
                *(float4*)&Vs[row * DD + c4 * 4] = v4;
            }
        }
        __syncthreads();

        // ---- QK: 4q x 4k per thread over d=0..127 ----
        float s[16];
        #pragma unroll
        for (int i = 0; i < 16; i++) s[i] = 0.f;
        #pragma unroll 4
        for (int d = 0; d < DD; d++) {
            float4 q4 = *(const float4*)&Qt[d * KT_STR + tq * 4];
            float4 k4 = *(const float4*)&Kt[d * KT_STR + tk * 4];
            s[0]  += q4.x * k4.x; s[1]  += q4.x * k4.y; s[2]  += q4.x * k4.z; s[3]  += q4.x * k4.w;
            s[4]  += q4.y * k4.x; s[5]  += q4.y * k4.y; s[6]  += q4.y * k4.z; s[7]  += q4.y * k4.w;
            s[8]  += q4.z * k4.x; s[9]  += q4.z * k4.y; s[10] += q4.z * k4.z; s[11] += q4.z * k4.w;
            s[12] += q4.w * k4.x; s[13] += q4.w * k4.y; s[14] += q4.w * k4.z; s[15] += q4.w * k4.w;
        }
        // mask + write scores
        int pk4[4];
        #pragma unroll
        for (int j = 0; j < 4; j++) pk4[j] = pos[kb + tk * 4 + j];
        #pragma unroll
        for (int i = 0; i < 4; i++) {
            float4 r;
            #pragma unroll
            for (int j = 0; j < 4; j++) {
                bool ok = (pk4[j] <= pq4[i]) && (pq4[i] - pk4[j] < WIN);
                ((float*)&r)[j] = ok ? s[i * 4 + j] : -1e30f;
            }
            *(float4*)&Ps[(tq * 4 + i) * P_STR + tk * 4] = r;
        }
        __syncthreads();

        // ---- Softmax update (crew layout: quad per query row) ----
        {
            float4 sv[4];
            float mx = -1e30f;
            #pragma unroll
            for (int u = 0; u < 4; u++) {
                sv[u] = *(const float4*)&Ps[ql * P_STR + g * 16 + 4 * u];
                mx = fmaxf(mx, fmaxf(fmaxf(sv[u].x, sv[u].y), fmaxf(sv[u].z, sv[u].w)));
            }
            mx = fmaxf(mx, __shfl_xor_sync(0xffffffffu, mx, 1));
            mx = fmaxf(mx, __shfl_xor_sync(0xffffffffu, mx, 2));
            float mold = Ms[ql];
            float mnew = fmaxf(mold, mx);
            float sum = 0.f;
            #pragma unroll
            for (int u = 0; u < 4; u++) {
                float4 p;
                p.x = __expf(sv[u].x - mnew);
                p.y = __expf(sv[u].y - mnew);
                p.z = __expf(sv[u].z - mnew);
                p.w = __expf(sv[u].w - mnew);
                sum += (p.x + p.y) + (p.z + p.w);
                *(float4*)&Ps[ql * P_STR + g * 16 + 4 * u] = p;
            }
            sum += __shfl_xor_sync(0xffffffffu, sum, 1);
            sum += __shfl_xor_sync(0xffffffffu, sum, 2);
            if (g == 0) {
                float scl = __expf(mold - mnew);
                Sc[ql] = scl;
                Ls[ql] = Ls[ql] * scl + sum;
                Ms[ql] = mnew;
            }
        }
        __syncthreads();

        // ---- PV: rescale o, then 4q x 8d over kk=0..63 ----
        #pragma unroll
        for (int i = 0; i < 4; i++) {
            float scl = Sc[tq * 4 + i];
            #pragma unroll
            for (int jj = 0; jj < 8; jj++) o[i * 8 + jj] *= scl;
        }
        #pragma unroll 2
        for (int kk = 0; kk < BN; kk++) {
            float4 va = *(const float4*)&Vs[kk * DD + tk * 4];
            float4 vb = *(const float4*)&Vs[kk * DD + 64 + tk * 4];
            #pragma unroll
            for (int i = 0; i < 4; i++) {
                float p = Ps[(tq * 4 + i) * P_STR + kk];
                o[i * 8 + 0] += p * va.x; o[i * 8 + 1] += p * va.y;
                o[i * 8 + 2] += p * va.z; o[i * 8 + 3] += p * va.w;
                o[i * 8 + 4] += p * vb.x; o[i * 8 + 5] += p * vb.y;
                o[i * 8 + 6] += p * vb.z; o[i * 8 + 7] += p * vb.w;
            }
        }
    }

    __syncthreads();   // Ls final
    #pragma unroll
    for (int i = 0; i < 4; i++) {
        int qg = q0 + tq * 4 + i;
        float invl = 1.0f / Ls[tq * 4 + i];
        float* op = out + ((size_t)qg * HH + h) * DD;
        float4 ra, rb;
        ra.x = o[i * 8 + 0] * invl; ra.y = o[i * 8 + 1] * invl;
        ra.z = o[i * 8 + 2] * invl; ra.w = o[i * 8 + 3] * invl;
        rb.x = o[i * 8 + 4] * invl; rb.y = o[i * 8 + 5] * invl;
        rb.z = o[i * 8 + 6] * invl; rb.w = o[i * 8 + 7] * invl;
        *(float4*)(op + tk * 4) = ra;
        *(float4*)(op + 64 + tk * 4) = rb;
    }
}

// ---------------------------------------------------------------------------
extern "C" void kernel_launch(void* const* d_in, const int* in_sizes, int n_in,
                              void* d_out, int out_size) {
    (void)in_sizes; (void)n_in; (void)out_size;
    const float* q     = (const float*)d_in[0];
    const float* k     = (const float*)d_in[1];
    const float* v     = (const float*)d_in[2];
    const int*   pos   = (const int*)d_in[3];
    const float* sinks = (const float*)d_in[4];
    float* out = (float*)d_out;

    rope_k_kernel<<<(KVHN * 64 * SS) / 256, 256>>>(k, pos);

    size_t smem = (size_t)(2 * DD * KT_STR + BN * DD + BM * P_STR + 3 * BM) * sizeof(float);
    cudaFuncSetAttribute(attn_kernel, cudaFuncAttributeMaxDynamicSharedMemorySize, (int)smem);
    dim3 grid(SS / BM, HH);
    attn_kernel<<<grid, 256, smem>>>(q, v, pos, sinks, out);
}

// round 5
// speedup vs baseline: 10.2884x; 1.6427x over previous
#include <cuda_runtime.h>
#include <math.h>
#include <stdint.h>

#define SS 2048
#define HH 32
#define KVHN 8
#define DD 128
#define BM 128
#define BN 64
#define WIN 1024
#define SCALE_F 0.08838834764831845f
#define L2K 13.287712379549449f
#define CFIX 16.0f

// smem float offsets
#define QS_OFF 0              // 128 x 132
#define KS_OFF 16896          // 64 x 132
#define VS_OFF 25344          // 64 x 132
#define PS_OFF 33792          // 128 x 68
#define PK_OFF 42496          // 64 ints
#define SMEM_FLOATS 42560

__device__ float g_kr[(size_t)SS * KVHN * DD];   // RoPE'd K, tf32-rounded, [s][kv][d]
__device__ float g_vr[(size_t)SS * KVHN * DD];   // V tf32-rounded, [s][kv][d]
__device__ float g_cs[SS * 64];
__device__ float g_sn[SS * 64];

__device__ __forceinline__ float tf32r(float x) {
    uint32_t u = __float_as_uint(x), o;
    asm("cvt.rna.tf32.f32 %0, %1;" : "=r"(o) : "r"(u));
    return __uint_as_float(o);
}

__device__ __forceinline__ void mma_tf32(float* d, uint32_t a0, uint32_t a1,
                                         uint32_t a2, uint32_t a3,
                                         uint32_t b0, uint32_t b1) {
    asm volatile(
        "mma.sync.aligned.m16n8k8.row.col.f32.tf32.tf32.f32 "
        "{%0,%1,%2,%3}, {%4,%5,%6,%7}, {%8,%9}, {%0,%1,%2,%3};"
        : "+f"(d[0]), "+f"(d[1]), "+f"(d[2]), "+f"(d[3])
        : "r"(a0), "r"(a1), "r"(a2), "r"(a3), "r"(b0), "r"(b1));
}

// ---------------------------------------------------------------------------
__global__ void tab_kernel(const int* __restrict__ pos) {
    int idx = blockIdx.x * blockDim.x + threadIdx.x;   // SS*64
    int i = idx & 63, s = idx >> 6;
    float inv = exp2f(-(float)i * (L2K / 64.f));
    float sn, cs;
    sincosf((float)pos[s] * inv, &sn, &cs);
    g_cs[idx] = cs;
    g_sn[idx] = sn;
}

__global__ void rope_k_kernel(const float* __restrict__ k) {
    int idx = blockIdx.x * blockDim.x + threadIdx.x;   // SS*KVHN*64
    int i = idx & 63;
    int kv = (idx >> 6) & 7;
    int s = idx >> 9;
    float cs = g_cs[s * 64 + i], sn = g_sn[s * 64 + i];
    const float* kp = k + ((size_t)s * KVHN + kv) * DD;
    float x1 = kp[i], x2 = kp[i + 64];
    float* op = g_kr + ((size_t)s * KVHN + kv) * DD;
    op[i]      = tf32r(x1 * cs - x2 * sn);
    op[i + 64] = tf32r(x2 * cs + x1 * sn);
}

__global__ void vr_kernel(const float* __restrict__ v) {
    int idx = blockIdx.x * blockDim.x + threadIdx.x;   // SS*KVHN*DD
    g_vr[idx] = tf32r(v[idx]);
}

// ---------------------------------------------------------------------------
extern __shared__ float sm[];

__global__ __launch_bounds__(256, 1) void attn_kernel(
    const float* __restrict__ q,
    const int* __restrict__ pos,
    const float* __restrict__ sinks,
    float* __restrict__ out)
{
    float* Qs = sm + QS_OFF;
    float* Ks = sm + KS_OFF;
    float* Vs = sm + VS_OFF;
    float* Ps = sm + PS_OFF;
    int*   PKs = (int*)(sm + PK_OFF);

    int tid = threadIdx.x;
    int wid = tid >> 5, lane = tid & 31;
    int lq = lane >> 2;              // quad row index 0..7
    int lr = lane & 3;               // index within quad
    int qt = blockIdx.x, h = blockIdx.y;
    int q0 = qt * BM, kvh = h >> 2;
    int w16 = wid * 16;

    // ---- Q prologue: RoPE + scale + tf32 round into Qs[row][d], str 132 ----
    {
        int row = tid >> 1, g = tid & 1;
        int qg = q0 + row;
        const float* qr = q + ((size_t)qg * HH + h) * DD;
        #pragma unroll
        for (int ii = 0; ii < 32; ii++) {
            int r = g * 32 + ii;
            float cs = g_cs[qg * 64 + r], sn = g_sn[qg * 64 + r];
            float x1 = qr[r], x2 = qr[r + 64];
            Qs[row * 132 + r]      = tf32r(SCALE_F * (x1 * cs - x2 * sn));
            Qs[row * 132 + r + 64] = tf32r(SCALE_F * (x2 * cs + x1 * sn));
        }
    }

    // softmax row positions for this thread's fragment rows
    int pq0 = pos[q0 + w16 + lq];
    int pq1 = pos[q0 + w16 + lq + 8];
    float den0 = 0.f, den1 = 0.f;

    float ofr[16][4];
    #pragma unroll
    for (int i = 0; i < 16; i++)
        #pragma unroll
        for (int j = 0; j < 4; j++) ofr[i][j] = 0.f;

    int kstart = q0 - (WIN - 1);
    if (kstart < 0) kstart = 0;
    kstart &= ~(BN - 1);
    int kend = q0 + BM;

    for (int kb = kstart; kb < kend; kb += BN) {
        __syncthreads();   // prev tile's PV done; Qs ready on first iter
        // ---- cooperative K/V tile load: 64 rows x 128 floats each ----
        #pragma unroll
        for (int j = 0; j < 8; j++) {
            int f = tid + 256 * j;
            int row = f >> 5, c4 = f & 31;
            const size_t gbase = ((size_t)(kb + row) * KVHN + kvh) * DD + c4 * 4;
            *(float4*)&Ks[row * 132 + c4 * 4] = *(const float4*)(g_kr + gbase);
            *(float4*)&Vs[row * 132 + c4 * 4] = *(const float4*)(g_vr + gbase);
        }
        if (tid < BN) PKs[tid] = pos[kb + tid];
        __syncthreads();

        // ---- QK: s[16x64] per warp via 16 k-steps x 8 n-blocks ----
        float sfr[8][4];
        #pragma unroll
        for (int i = 0; i < 8; i++)
            #pragma unroll
            for (int j = 0; j < 4; j++) sfr[i][j] = 0.f;

        #pragma unroll 4
        for (int ks = 0; ks < 16; ks++) {
            int ab = (w16 + lq) * 132 + ks * 8 + lr;
            uint32_t a0 = __float_as_uint(Qs[ab]);
            uint32_t a2 = __float_as_uint(Qs[ab + 4]);
            uint32_t a1 = __float_as_uint(Qs[ab + 8 * 132]);
            uint32_t a3 = __float_as_uint(Qs[ab + 8 * 132 + 4]);
            #pragma unroll
            for (int nb = 0; nb < 8; nb++) {
                int bb = (nb * 8 + lq) * 132 + ks * 8 + lr;
                uint32_t b0 = __float_as_uint(Ks[bb]);
                uint32_t b1 = __float_as_uint(Ks[bb + 4]);
                mma_tf32(sfr[nb], a0, a1, a2, a3, b0, b1);
            }
        }

        // ---- softmax: p = exp(s - CFIX), masked; write tf32 P to Ps ----
        #pragma unroll
        for (int nb = 0; nb < 8; nb++) {
            int c0 = nb * 8 + 2 * lr;
            int pk0 = PKs[c0], pk1 = PKs[c0 + 1];
            float p0 = (pk0 <= pq0 && pq0 - pk0 < WIN) ? __expf(sfr[nb][0] - CFIX) : 0.f;
            float p1 = (pk1 <= pq0 && pq0 - pk1 < WIN) ? __expf(sfr[nb][1] - CFIX) : 0.f;
            float p2 = (pk0 <= pq1 && pq1 - pk0 < WIN) ? __expf(sfr[nb][2] - CFIX) : 0.f;
            float p3 = (pk1 <= pq1 && pq1 - pk1 < WIN) ? __expf(sfr[nb][3] - CFIX) : 0.f;
            den0 += p0 + p1;
            den1 += p2 + p3;
            float2 r0 = make_float2(tf32r(p0), tf32r(p1));
            float2 r1 = make_float2(tf32r(p2), tf32r(p3));
            *(float2*)&Ps[(w16 + lq) * 68 + c0]     = r0;
            *(float2*)&Ps[(w16 + lq + 8) * 68 + c0] = r1;
        }
        // Ps rows are warp-private: no block sync needed before PV.

        // ---- PV: o[16x128] += P[16x64] x V[64x128] ----
        #pragma unroll 2
        for (int ks = 0; ks < 8; ks++) {
            int ab = (w16 + lq) * 68 + ks * 8 + lr;
            uint32_t a0 = __float_as_uint(Ps[ab]);
            uint32_t a2 = __float_as_uint(Ps[ab + 4]);
            uint32_t a1 = __float_as_uint(Ps[ab + 8 * 68]);
            uint32_t a3 = __float_as_uint(Ps[ab + 8 * 68 + 4]);
            #pragma unroll
            for (int nb = 0; nb < 16; nb++) {
                int bb = (ks * 8 + lr) * 132 + nb * 8 + lq;
                uint32_t b0 = __float_as_uint(Vs[bb]);
                uint32_t b1 = __float_as_uint(Vs[bb + 4 * 132]);
                mma_tf32(ofr[nb], a0, a1, a2, a3, b0, b1);
            }
        }
    }

    // ---- epilogue: reduce denominators within quads, add sink, write out ----
    den0 += __shfl_xor_sync(0xffffffffu, den0, 1);
    den0 += __shfl_xor_sync(0xffffffffu, den0, 2);
    den1 += __shfl_xor_sync(0xffffffffu, den1, 1);
    den1 += __shfl_xor_sync(0xffffffffu, den1, 2);
    float sk = __expf(sinks[h] - CFIX);
    float inv0 = 1.0f / (den0 + sk);
    float inv1 = 1.0f / (den1 + sk);

    int row0 = q0 + w16 + lq;
    int row1 = row0 + 8;
    float* op0 = out + ((size_t)row0 * HH + h) * DD;
    float* op1 = out + ((size_t)row1 * HH + h) * DD;
    #pragma unroll
    for (int nb = 0; nb < 16; nb++) {
        int c = nb * 8 + 2 * lr;
        *(float2*)(op0 + c) = make_float2(ofr[nb][0] * inv0, ofr[nb][1] * inv0);
        *(float2*)(op1 + c) = make_float2(ofr[nb][2] * inv1, ofr[nb][3] * inv1);
    }
}

// ---------------------------------------------------------------------------
extern "C" void kernel_launch(void* const* d_in, const int* in_sizes, int n_in,
                              void* d_out, int out_size) {
    (void)in_sizes; (void)n_in; (void)out_size;
    const float* q     = (const float*)d_in[0];
    const float* k     = (const float*)d_in[1];
    const float* v     = (const float*)d_in[2];
    const int*   pos   = (const int*)d_in[3];
    const float* sinks = (const float*)d_in[4];
    float* out = (float*)d_out;

    tab_kernel<<<(SS * 64) / 256, 256>>>(pos);
    rope_k_kernel<<<(SS * KVHN * 64) / 256, 256>>>(k);
    vr_kernel<<<(SS * KVHN * DD) / 256, 256>>>(v);

    size_t smem = SMEM_FLOATS * sizeof(float);
    cudaFuncSetAttribute(attn_kernel, cudaFuncAttributeMaxDynamicSharedMemorySize, (int)smem);
    dim3 grid(SS / BM, HH);
    attn_kernel<<<grid, 256, smem>>>(q, pos, sinks, out);
}

// round 9
// speedup vs baseline: 24.8359x; 2.4140x over previous
#include <cuda_runtime.h>
#include <cuda_fp16.h>
#include <math.h>
#include <stdint.h>

#define SS 2048
#define HH 32
#define KVHN 8
#define DD 128
#define BM 128
#define BN 64
#define WIN 1024
#define SCALE_F 0.08838834764831845f
#define L2K 13.287712379549449f
#define CFIX 4.0f

#define STRQ 136            // half stride for Q/K/V rows (272B -> 4-quad step)
#define STRP 72             // half stride for P rows (144B -> 4-quad step)

// smem half offsets
#define QS_OFF 0                          // 128 x STRQ
#define KS_OFF (128 * STRQ)               // 64 x STRQ
#define VS_OFF (KS_OFF + 64 * STRQ)       // 64 x STRQ
#define PS_OFF (VS_OFF + 64 * STRQ)       // 128 x STRP
#define PK_OFF (PS_OFF + 128 * STRP)      // 64 ints (as 128 halves)
#define SMEM_HALVES (PK_OFF + 128)

__device__ __half g_kr[(size_t)SS * KVHN * DD];   // RoPE'd K fp16, [s][kv][d]
__device__ __half g_vr[(size_t)SS * KVHN * DD];   // V fp16, [s][kv][d]
__device__ float g_cs[SS * 64];
__device__ float g_sn[SS * 64];

__device__ __forceinline__ uint32_t smem_u32(const void* p) {
    uint32_t a;
    asm("{ .reg .u64 t; cvta.to.shared.u64 t, %1; cvt.u32.u64 %0, t; }" : "=r"(a) : "l"(p));
    return a;
}
__device__ __forceinline__ void ldm_x4(uint32_t* r, uint32_t a) {
    asm volatile("ldmatrix.sync.aligned.m8n8.x4.shared.b16 {%0,%1,%2,%3}, [%4];"
        : "=r"(r[0]), "=r"(r[1]), "=r"(r[2]), "=r"(r[3]) : "r"(a));
}
__device__ __forceinline__ void ldm_x4_t(uint32_t* r, uint32_t a) {
    asm volatile("ldmatrix.sync.aligned.m8n8.x4.trans.shared.b16 {%0,%1,%2,%3}, [%4];"
        : "=r"(r[0]), "=r"(r[1]), "=r"(r[2]), "=r"(r[3]) : "r"(a));
}
__device__ __forceinline__ void mma_f16(float* d, const uint32_t* a, uint32_t b0, uint32_t b1) {
    asm volatile(
        "mma.sync.aligned.m16n8k16.row.col.f32.f16.f16.f32 "
        "{%0,%1,%2,%3}, {%4,%5,%6,%7}, {%8,%9}, {%0,%1,%2,%3};"
        : "+f"(d[0]), "+f"(d[1]), "+f"(d[2]), "+f"(d[3])
        : "r"(a[0]), "r"(a[1]), "r"(a[2]), "r"(a[3]), "r"(b0), "r"(b1));
}

// ---------------------------------------------------------------------------
__global__ void tab_kernel(const int* __restrict__ pos) {
    int idx = blockIdx.x * blockDim.x + threadIdx.x;   // SS*64
    int i = idx & 63, s = idx >> 6;
    float inv = exp2f(-(float)i * (L2K / 64.f));
    float sn, cs;
    sincosf((float)pos[s] * inv, &sn, &cs);
    g_cs[idx] = cs;
    g_sn[idx] = sn;
}

__global__ void rope_k_kernel(const float* __restrict__ k) {
    int idx = blockIdx.x * blockDim.x + threadIdx.x;   // SS*KVHN*64
    int i = idx & 63;
    int kv = (idx >> 6) & 7;
    int s = idx >> 9;
    float cs = g_cs[s * 64 + i], sn = g_sn[s * 64 + i];
    const float* kp = k + ((size_t)s * KVHN + kv) * DD;
    float x1 = kp[i], x2 = kp[i + 64];
    __half* op = g_kr + ((size_t)s * KVHN + kv) * DD;
    op[i]      = __float2half_rn(x1 * cs - x2 * sn);
    op[i + 64] = __float2half_rn(x2 * cs + x1 * sn);
}

__global__ void vr_kernel(const float* __restrict__ v) {
    int idx = blockIdx.x * blockDim.x + threadIdx.x;   // SS*KVHN*DD
    g_vr[idx] = __float2half_rn(v[idx]);
}

// ---------------------------------------------------------------------------
extern __shared__ __half smh[];

__global__ __launch_bounds__(256, 1) void attn_kernel(
    const float* __restrict__ q,
    const int* __restrict__ pos,
    const float* __restrict__ sinks,
    float* __restrict__ out)
{
    __half* Qs = smh + QS_OFF;
    __half* Ks = smh + KS_OFF;
    __half* Vs = smh + VS_OFF;
    __half* Ps = smh + PS_OFF;
    int*    PKs = (int*)(smh + PK_OFF);

    int tid = threadIdx.x;
    int wid = tid >> 5, lane = tid & 31;
    int lq = lane >> 2;              // 0..7
    int lr = lane & 3;               // 0..3
    int qt = blockIdx.x, h = blockIdx.y;
    int q0 = qt * BM, kvh = h >> 2;
    int w16 = wid * 16;

    uint32_t qs_b = smem_u32(Qs), ks_b = smem_u32(Ks);
    uint32_t vs_b = smem_u32(Vs), ps_b = smem_u32(Ps);

    // per-lane ldmatrix address components
    int l15 = lane & 15, lh = (lane >> 4) & 1;      // A pattern
    int l7 = lane & 7, l8 = (lane >> 3) & 1;        // B patterns
    uint32_t qa_base = qs_b + (uint32_t)(((w16 + l15) * STRQ + lh * 8) * 2);
    uint32_t ka_base = ks_b + (uint32_t)(((l7 + lh * 8) * STRQ + l8 * 8) * 2);
    uint32_t pa_base = ps_b + (uint32_t)(((w16 + l15) * STRP + lh * 8) * 2);
    uint32_t va_base = vs_b + (uint32_t)(((l7 + l8 * 8) * STRQ + lh * 8) * 2);

    // ---- Q prologue: RoPE + scale -> fp16 Qs ----
    {
        int row = tid >> 1, g = tid & 1;
        int qg = q0 + row;
        const float* qr = q + ((size_t)qg * HH + h) * DD;
        #pragma unroll
        for (int ii = 0; ii < 32; ii++) {
            int r = g * 32 + ii;
            float cs = g_cs[qg * 64 + r], sn = g_sn[qg * 64 + r];
            float x1 = qr[r], x2 = qr[r + 64];
            Qs[row * STRQ + r]      = __float2half_rn(SCALE_F * (x1 * cs - x2 * sn));
            Qs[row * STRQ + r + 64] = __float2half_rn(SCALE_F * (x2 * cs + x1 * sn));
        }
    }

    int pq0 = pos[q0 + w16 + lq];
    int pq1 = pos[q0 + w16 + lq + 8];
    float den0 = 0.f, den1 = 0.f;

    float ofr[16][4];
    #pragma unroll
    for (int i = 0; i < 16; i++)
        #pragma unroll
        for (int j = 0; j < 4; j++) ofr[i][j] = 0.f;

    int kstart = q0 - (WIN - 1);
    if (kstart < 0) kstart = 0;
    kstart &= ~(BN - 1);
    int kend = q0 + BM;

    for (int kb = kstart; kb < kend; kb += BN) {
        __syncthreads();
        // ---- cooperative K/V tile load: 64 rows x 128 halves each ----
        #pragma unroll
        for (int j = 0; j < 4; j++) {
            int f = tid + 256 * j;
            int row = f >> 4, c = f & 15;          // c: 16B chunk (8 halves)
            const size_t gbase = ((size_t)(kb + row) * KVHN + kvh) * DD + c * 8;
            *(uint4*)&Ks[row * STRQ + c * 8] = *(const uint4*)(g_kr + gbase);
            *(uint4*)&Vs[row * STRQ + c * 8] = *(const uint4*)(g_vr + gbase);
        }
        if (tid < BN) PKs[tid] = pos[kb + tid];
        __syncthreads();

        // ---- QK: s[16x64] per warp; 8 k16-steps x 8 n-blocks ----
        float sfr[8][4];
        #pragma unroll
        for (int i = 0; i < 8; i++)
            #pragma unroll
            for (int j = 0; j < 4; j++) sfr[i][j] = 0.f;

        #pragma unroll
        for (int ks = 0; ks < 8; ks++) {
            uint32_t a[4];
            ldm_x4(a, qa_base + ks * 32);          // ks*16 halves = 32B
            #pragma unroll
            for (int nbp = 0; nbp < 4; nbp++) {
                uint32_t b[4];
                ldm_x4(b, ka_base + (uint32_t)((nbp * 16 * STRQ) * 2) + ks * 32);
                mma_f16(sfr[2 * nbp],     a, b[0], b[1]);
                mma_f16(sfr[2 * nbp + 1], a, b[2], b[3]);
            }
        }

        // ---- softmax: p = exp(s - CFIX), masked; fp16 P -> Ps ----
        #pragma unroll
        for (int nb = 0; nb < 8; nb++) {
            int c0 = nb * 8 + 2 * lr;
            int pk0 = PKs[c0], pk1 = PKs[c0 + 1];
            float p0 = (pk0 <= pq0 && pq0 - pk0 < WIN) ? __expf(sfr[nb][0] - CFIX) : 0.f;
            float p1 = (pk1 <= pq0 && pq0 - pk1 < WIN) ? __expf(sfr[nb][1] - CFIX) : 0.f;
            float p2 = (pk0 <= pq1 && pq1 - pk0 < WIN) ? __expf(sfr[nb][2] - CFIX) : 0.f;
            float p3 = (pk1 <= pq1 && pq1 - pk1 < WIN) ? __expf(sfr[nb][3] - CFIX) : 0.f;
            den0 += p0 + p1;
            den1 += p2 + p3;
            *(__half2*)&Ps[(w16 + lq) * STRP + c0]     = __floats2half2_rn(p0, p1);
            *(__half2*)&Ps[(w16 + lq + 8) * STRP + c0] = __floats2half2_rn(p2, p3);
        }
        __syncwarp();   // Ps rows warp-private; make stores visible to ldmatrix

        // ---- PV: o[16x128] += P[16x64] x V[64x128]; 4 k16-steps x 16 nb ----
        #pragma unroll
        for (int ks = 0; ks < 4; ks++) {
            uint32_t a[4];
            ldm_x4(a, pa_base + ks * 32);
            #pragma unroll
            for (int nbp = 0; nbp < 8; nbp++) {
                uint32_t b[4];
                ldm_x4_t(b, va_base + (uint32_t)((ks * 16 * STRQ + nbp * 16) * 2));
                mma_f16(ofr[2 * nbp],     a, b[0], b[1]);
                mma_f16(ofr[2 * nbp + 1], a, b[2], b[3]);
            }
        }
    }

    // ---- epilogue ----
    den0 += __shfl_xor_sync(0xffffffffu, den0, 1);
    den0 += __shfl_xor_sync(0xffffffffu, den0, 2);
    den1 += __shfl_xor_sync(0xffffffffu, den1, 1);
    den1 += __shfl_xor_sync(0xffffffffu, den1, 2);
    float sk = __expf(sinks[h] - CFIX);
    float inv0 = 1.0f / (den0 + sk);
    float inv1 = 1.0f / (den1 + sk);

    int row0 = q0 + w16 + lq;
    int row1 = row0 + 8;
    float* op0 = out + ((size_t)row0 * HH + h) * DD;
    float* op1 = out + ((size_t)row1 * HH + h) * DD;
    #pragma unroll
    for (int nb = 0; nb < 16; nb++) {
        int c = nb * 8 + 2 * lr;
        *(float2*)(op0 + c) = make_float2(ofr[nb][0] * inv0, ofr[nb][1] * inv0);
        *(float2*)(op1 + c) = make_float2(ofr[nb][2] * inv1, ofr[nb][3] * inv1);
    }
}

// ---------------------------------------------------------------------------
extern "C" void kernel_launch(void* const* d_in, const int* in_sizes, int n_in,
                              void* d_out, int out_size) {
    (void)in_sizes; (void)n_in; (void)out_size;
    const float* q     = (const float*)d_in[0];
    const float* k     = (const float*)d_in[1];
    const float* v     = (const float*)d_in[2];
    const int*   pos   = (const int*)d_in[3];
    const float* sinks = (const float*)d_in[4];
    float* out = (float*)d_out;

    tab_kernel<<<(SS * 64) / 256, 256>>>(pos);
    rope_k_kernel<<<(SS * KVHN * 64) / 256, 256>>>(k);
    vr_kernel<<<(SS * KVHN * DD) / 256, 256>>>(v);

    size_t smem = SMEM_HALVES * sizeof(__half);
    cudaFuncSetAttribute(attn_kernel, cudaFuncAttributeMaxDynamicSharedMemorySize, (int)smem);
    dim3 grid(SS / BM, HH);
    attn_kernel<<<grid, 256, smem>>>(q, pos, sinks, out);
}

// round 10
// speedup vs baseline: 25.7757x; 1.0378x over previous
#include <cuda_runtime.h>
#include <cuda_fp16.h>
#include <math.h>
#include <stdint.h>

#define SS 2048
#define HH 32
#define KVHN 8
#define DD 128
#define BM 128
#define BN 64
#define WIN 1024
#define SCALE_F 0.08838834764831845f
#define L2K 13.287712379549449f
#define CFIX 4.0f

#define STRQ 136            // half stride for Q/K/V rows (272B -> 4-quad step)
#define STRP 72             // half stride for P rows

// smem half offsets
#define QS_OFF 0                           // 128 x STRQ
#define KS0_OFF (128 * STRQ)               // 64 x STRQ (buf 0)
#define KS1_OFF (KS0_OFF + 64 * STRQ)      // 64 x STRQ (buf 1)
#define VS0_OFF (KS1_OFF + 64 * STRQ)
#define VS1_OFF (VS0_OFF + 64 * STRQ)
#define PS_OFF  (VS1_OFF + 64 * STRQ)      // 128 x STRP
#define PK0_OFF (PS_OFF + 128 * STRP)      // 64 ints = 128 halves
#define PK1_OFF (PK0_OFF + 128)
#define SMEM_HALVES (PK1_OFF + 128)

__device__ __half g_kr[(size_t)SS * KVHN * DD];   // RoPE'd K fp16, [s][kv][d]
__device__ __half g_vr[(size_t)SS * KVHN * DD];   // V fp16, [s][kv][d]
__device__ float g_cs[SS * 64];
__device__ float g_sn[SS * 64];

__device__ __forceinline__ uint32_t smem_u32(const void* p) {
    uint32_t a;
    asm("{ .reg .u64 t; cvta.to.shared.u64 t, %1; cvt.u32.u64 %0, t; }" : "=r"(a) : "l"(p));
    return a;
}
__device__ __forceinline__ void cp16(uint32_t dst, const void* src) {
    asm volatile("cp.async.cg.shared.global [%0], [%1], 16;" :: "r"(dst), "l"(src));
}
__device__ __forceinline__ void cp_commit() {
    asm volatile("cp.async.commit_group;" ::: "memory");
}
__device__ __forceinline__ void cp_wait0() {
    asm volatile("cp.async.wait_group 0;" ::: "memory");
}
__device__ __forceinline__ void ldm_x4(uint32_t* r, uint32_t a) {
    asm volatile("ldmatrix.sync.aligned.m8n8.x4.shared.b16 {%0,%1,%2,%3}, [%4];"
        : "=r"(r[0]), "=r"(r[1]), "=r"(r[2]), "=r"(r[3]) : "r"(a));
}
__device__ __forceinline__ void ldm_x4_t(uint32_t* r, uint32_t a) {
    asm volatile("ldmatrix.sync.aligned.m8n8.x4.trans.shared.b16 {%0,%1,%2,%3}, [%4];"
        : "=r"(r[0]), "=r"(r[1]), "=r"(r[2]), "=r"(r[3]) : "r"(a));
}
__device__ __forceinline__ void mma_f16(float* d, const uint32_t* a, uint32_t b0, uint32_t b1) {
    asm volatile(
        "mma.sync.aligned.m16n8k16.row.col.f32.f16.f16.f32 "
        "{%0,%1,%2,%3}, {%4,%5,%6,%7}, {%8,%9}, {%0,%1,%2,%3};"
        : "+f"(d[0]), "+f"(d[1]), "+f"(d[2]), "+f"(d[3])
        : "r"(a[0]), "r"(a[1]), "r"(a[2]), "r"(a[3]), "r"(b0), "r"(b1));
}

// ---------------------------------------------------------------------------
__global__ void tab_kernel(const int* __restrict__ pos) {
    int idx = blockIdx.x * blockDim.x + threadIdx.x;   // SS*64
    int i = idx & 63, s = idx >> 6;
    float inv = exp2f(-(float)i * (L2K / 64.f));
    float sn, cs;
    sincosf((float)pos[s] * inv, &sn, &cs);
    g_cs[idx] = cs;
    g_sn[idx] = sn;
}

__global__ void rope_k_kernel(const float* __restrict__ k) {
    int idx = blockIdx.x * blockDim.x + threadIdx.x;   // SS*KVHN*64
    int i = idx & 63;
    int kv = (idx >> 6) & 7;
    int s = idx >> 9;
    float cs = g_cs[s * 64 + i], sn = g_sn[s * 64 + i];
    const float* kp = k + ((size_t)s * KVHN + kv) * DD;
    float x1 = kp[i], x2 = kp[i + 64];
    __half* op = g_kr + ((size_t)s * KVHN + kv) * DD;
    op[i]      = __float2half_rn(x1 * cs - x2 * sn);
    op[i + 64] = __float2half_rn(x2 * cs + x1 * sn);
}

__global__ void vr_kernel(const float* __restrict__ v) {
    int idx = blockIdx.x * blockDim.x + threadIdx.x;   // SS*KVHN*DD
    g_vr[idx] = __float2half_rn(v[idx]);
}

// ---------------------------------------------------------------------------
extern __shared__ __half smh[];

__global__ __launch_bounds__(256, 1) void attn_kernel(
    const float* __restrict__ q,
    const int* __restrict__ pos,
    const float* __restrict__ sinks,
    float* __restrict__ out)
{
    __half* Qs = smh + QS_OFF;
    __half* Ps = smh + PS_OFF;

    int tid = threadIdx.x;
    int wid = tid >> 5, lane = tid & 31;
    int lq = lane >> 2;
    int lr = lane & 3;
    int qt = blockIdx.x, h = blockIdx.y;
    int q0 = qt * BM, kvh = h >> 2;
    int w16 = wid * 16;

    uint32_t qs_b = smem_u32(Qs), ps_b = smem_u32(Ps);
    uint32_t ks_b[2] = { smem_u32(smh + KS0_OFF), smem_u32(smh + KS1_OFF) };
    uint32_t vs_b[2] = { smem_u32(smh + VS0_OFF), smem_u32(smh + VS1_OFF) };
    uint32_t pk_b[2] = { smem_u32(smh + PK0_OFF), smem_u32(smh + PK1_OFF) };
    const int* PK0 = (const int*)(smh + PK0_OFF);
    const int* PK1 = (const int*)(smh + PK1_OFF);

    // per-lane ldmatrix address components
    int l15 = lane & 15, lh = (lane >> 4) & 1;
    int l7 = lane & 7, l8 = (lane >> 3) & 1;
    uint32_t qa_base = qs_b + (uint32_t)(((w16 + l15) * STRQ + lh * 8) * 2);
    uint32_t pa_base = ps_b + (uint32_t)(((w16 + l15) * STRP + lh * 8) * 2);
    uint32_t ka_off = (uint32_t)(((l7 + lh * 8) * STRQ + l8 * 8) * 2);
    uint32_t va_off = (uint32_t)(((l7 + l8 * 8) * STRQ + lh * 8) * 2);

    // cp.async prefetch slots for this thread (4 x 16B chunks each for K and V)
    int pf_row[4], pf_c[4];
    #pragma unroll
    for (int j = 0; j < 4; j++) {
        int f = tid + 256 * j;
        pf_row[j] = f >> 4;
        pf_c[j] = f & 15;
    }

    // ---- Q prologue: RoPE + scale -> fp16 Qs ----
    {
        int row = tid >> 1, g = tid & 1;
        int qg = q0 + row;
        const float* qr = q + ((size_t)qg * HH + h) * DD;
        #pragma unroll
        for (int ii = 0; ii < 32; ii++) {
            int r = g * 32 + ii;
            float cs = g_cs[qg * 64 + r], sn = g_sn[qg * 64 + r];
            float x1 = qr[r], x2 = qr[r + 64];
            Qs[row * STRQ + r]      = __float2half_rn(SCALE_F * (x1 * cs - x2 * sn));
            Qs[row * STRQ + r + 64] = __float2half_rn(SCALE_F * (x2 * cs + x1 * sn));
        }
    }

    int pq0 = pos[q0 + w16 + lq];
    int pq1 = pos[q0 + w16 + lq + 8];
    float den0 = 0.f, den1 = 0.f;

    float ofr[16][4];
    #pragma unroll
    for (int i = 0; i < 16; i++)
        #pragma unroll
        for (int j = 0; j < 4; j++) ofr[i][j] = 0.f;

    int kstart = q0 - (WIN - 1);
    if (kstart < 0) kstart = 0;
    kstart &= ~(BN - 1);
    int nt = (q0 + BM - kstart) / BN;

    // ---- prefetch tile 0 into buffer 0 ----
    {
        int kb = kstart;
        #pragma unroll
        for (int j = 0; j < 4; j++) {
            const size_t gb = ((size_t)(kb + pf_row[j]) * KVHN + kvh) * DD + pf_c[j] * 8;
            uint32_t so = (uint32_t)((pf_row[j] * STRQ + pf_c[j] * 8) * 2);
            cp16(ks_b[0] + so, g_kr + gb);
            cp16(vs_b[0] + so, g_vr + gb);
        }
        if (tid < 16) cp16(pk_b[0] + tid * 16, (const char*)(pos + kb) + tid * 16);
        cp_commit();
    }

    for (int it = 0; it < nt; it++) {
        int b = it & 1;
        cp_wait0();
        __syncthreads();     // tile `it` published to all warps; prev reads of buf b^1 done

        // ---- prefetch tile it+1 into the other buffer ----
        if (it + 1 < nt) {
            int kb = kstart + (it + 1) * BN;
            #pragma unroll
            for (int j = 0; j < 4; j++) {
                const size_t gb = ((size_t)(kb + pf_row[j]) * KVHN + kvh) * DD + pf_c[j] * 8;
                uint32_t so = (uint32_t)((pf_row[j] * STRQ + pf_c[j] * 8) * 2);
                cp16(ks_b[b ^ 1] + so, g_kr + gb);
                cp16(vs_b[b ^ 1] + so, g_vr + gb);
            }
            if (tid < 16) cp16(pk_b[b ^ 1] + tid * 16, (const char*)(pos + kb) + tid * 16);
            cp_commit();
        }

        uint32_t ka_base = ks_b[b] + ka_off;
        uint32_t va_base = vs_b[b] + va_off;
        const int* PKs = b ? PK1 : PK0;

        // ---- QK: s[16x64] per warp; 8 k16-steps x 8 n-blocks ----
        float sfr[8][4];
        #pragma unroll
        for (int i = 0; i < 8; i++)
            #pragma unroll
            for (int j = 0; j < 4; j++) sfr[i][j] = 0.f;

        #pragma unroll
        for (int ks = 0; ks < 8; ks++) {
            uint32_t a[4];
            ldm_x4(a, qa_base + ks * 32);
            #pragma unroll
            for (int nbp = 0; nbp < 4; nbp++) {
                uint32_t bfr[4];
                ldm_x4(bfr, ka_base + (uint32_t)((nbp * 16 * STRQ) * 2) + ks * 32);
                mma_f16(sfr[2 * nbp],     a, bfr[0], bfr[1]);
                mma_f16(sfr[2 * nbp + 1], a, bfr[2], bfr[3]);
            }
        }

        // ---- softmax: p = exp(s - CFIX), masked; fp16 P -> Ps ----
        #pragma unroll
        for (int nb = 0; nb < 8; nb++) {
            int c0 = nb * 8 + 2 * lr;
            int pk0 = PKs[c0], pk1 = PKs[c0 + 1];
            float p0 = (pk0 <= pq0 && pq0 - pk0 < WIN) ? __expf(sfr[nb][0] - CFIX) : 0.f;
            float p1 = (pk1 <= pq0 && pq0 - pk1 < WIN) ? __expf(sfr[nb][1] - CFIX) : 0.f;
            float p2 = (pk0 <= pq1 && pq1 - pk0 < WIN) ? __expf(sfr[nb][2] - CFIX) : 0.f;
            float p3 = (pk1 <= pq1 && pq1 - pk1 < WIN) ? __expf(sfr[nb][3] - CFIX) : 0.f;
            den0 += p0 + p1;
            den1 += p2 + p3;
            *(__half2*)&Ps[(w16 + lq) * STRP + c0]     = __floats2half2_rn(p0, p1);
            *(__half2*)&Ps[(w16 + lq + 8) * STRP + c0] = __floats2half2_rn(p2, p3);
        }
        __syncwarp();   // Ps rows warp-private

        // ---- PV: o[16x128] += P[16x64] x V[64x128] ----
        #pragma unroll
        for (int ks = 0; ks < 4; ks++) {
            uint32_t a[4];
            ldm_x4(a, pa_base + ks * 32);
            #pragma unroll
            for (int nbp = 0; nbp < 8; nbp++) {
                uint32_t bfr[4];
                ldm_x4_t(bfr, va_base + (uint32_t)((ks * 16 * STRQ + nbp * 16) * 2));
                mma_f16(ofr[2 * nbp],     a, bfr[0], bfr[1]);
                mma_f16(ofr[2 * nbp + 1], a, bfr[2], bfr[3]);
            }
        }
        __syncthreads();   // all warps done reading buf b before it is refilled next+1 iter
    }

    // ---- epilogue ----
    den0 += __shfl_xor_sync(0xffffffffu, den0, 1);
    den0 += __shfl_xor_sync(0xffffffffu, den0, 2);
    den1 += __shfl_xor_sync(0xffffffffu, den1, 1);
    den1 += __shfl_xor_sync(0xffffffffu, den1, 2);
    float sk = __expf(sinks[h] - CFIX);
    float inv0 = 1.0f / (den0 + sk);
    float inv1 = 1.0f / (den1 + sk);

    int row0 = q0 + w16 + lq;
    int row1 = row0 + 8;
    float* op0 = out + ((size_t)row0 * HH + h) * DD;
    float* op1 = out + ((size_t)row1 * HH + h) * DD;
    #pragma unroll
    for (int nb = 0; nb < 16; nb++) {
        int c = nb * 8 + 2 * lr;
        *(float2*)(op0 + c) = make_float2(ofr[nb][0] * inv0, ofr[nb][1] * inv0);
        *(float2*)(op1 + c) = make_float2(ofr[nb][2] * inv1, ofr[nb][3] * inv1);
    }
}

// ---------------------------------------------------------------------------
extern "C" void kernel_launch(void* const* d_in, const int* in_sizes, int n_in,
                              void* d_out, int out_size) {
    (void)in_sizes; (void)n_in; (void)out_size;
    const float* q     = (const float*)d_in[0];
    const float* k     = (const float*)d_in[1];
    const float* v     = (const float*)d_in[2];
    const int*   pos   = (const int*)d_in[3];
    const float* sinks = (const float*)d_in[4];
    float* out = (float*)d_out;

    tab_kernel<<<(SS * 64) / 256, 256>>>(pos);
    rope_k_kernel<<<(SS * KVHN * 64) / 256, 256>>>(k);
    vr_kernel<<<(SS * KVHN * DD) / 256, 256>>>(v);

    size_t smem = SMEM_HALVES * sizeof(__half);
    cudaFuncSetAttribute(attn_kernel, cudaFuncAttributeMaxDynamicSharedMemorySize, (int)smem);
    dim3 grid(SS / BM, HH);
    attn_kernel<<<grid, 256, smem>>>(q, pos, sinks, out);
}

// round 11
// speedup vs baseline: 30.8464x; 1.1967x over previous
#include <cuda_runtime.h>
#include <cuda_fp16.h>
#include <math.h>
#include <stdint.h>

#define SS 2048
#define HH 32
#define KVHN 8
#define DD 128
#define BM 128
#define BN 64
#define WIN 1024
#define SCALE_F 0.08838834764831845f
#define L2K 13.287712379549449f
#define CFIX 4.0f

#define STRQ 136            // half stride for Q/K/V rows (272B -> 4-quad step)
#define STRP 72             // half stride for P rows

// smem half offsets
#define QS_OFF 0                           // 128 x STRQ
#define KS0_OFF (128 * STRQ)               // 64 x STRQ (buf 0)
#define KS1_OFF (KS0_OFF + 64 * STRQ)
#define VS0_OFF (KS1_OFF + 64 * STRQ)
#define VS1_OFF (VS0_OFF + 64 * STRQ)
#define PS_OFF  (VS1_OFF + 64 * STRQ)      // 128 x STRP
#define PK0_OFF (PS_OFF + 128 * STRP)      // 64 ints = 128 halves
#define PK1_OFF (PK0_OFF + 128)
#define DEN_OFF (PK1_OFF + 128)            // 256 floats = 512 halves
#define SMEM_HALVES (DEN_OFF + 512)

__device__ __half g_kr[(size_t)SS * KVHN * DD];   // RoPE'd K fp16, [s][kv][d]
__device__ __half g_vr[(size_t)SS * KVHN * DD];   // V fp16, [s][kv][d]
__device__ float g_cs[SS * 64];
__device__ float g_sn[SS * 64];

__device__ __forceinline__ uint32_t smem_u32(const void* p) {
    uint32_t a;
    asm("{ .reg .u64 t; cvta.to.shared.u64 t, %1; cvt.u32.u64 %0, t; }" : "=r"(a) : "l"(p));
    return a;
}
__device__ __forceinline__ void cp16(uint32_t dst, const void* src) {
    asm volatile("cp.async.cg.shared.global [%0], [%1], 16;" :: "r"(dst), "l"(src));
}
__device__ __forceinline__ void cp_commit() {
    asm volatile("cp.async.commit_group;" ::: "memory");
}
__device__ __forceinline__ void cp_wait0() {
    asm volatile("cp.async.wait_group 0;" ::: "memory");
}
__device__ __forceinline__ void ldm_x4(uint32_t* r, uint32_t a) {
    asm volatile("ldmatrix.sync.aligned.m8n8.x4.shared.b16 {%0,%1,%2,%3}, [%4];"
        : "=r"(r[0]), "=r"(r[1]), "=r"(r[2]), "=r"(r[3]) : "r"(a));
}
__device__ __forceinline__ void ldm_x4_t(uint32_t* r, uint32_t a) {
    asm volatile("ldmatrix.sync.aligned.m8n8.x4.trans.shared.b16 {%0,%1,%2,%3}, [%4];"
        : "=r"(r[0]), "=r"(r[1]), "=r"(r[2]), "=r"(r[3]) : "r"(a));
}
__device__ __forceinline__ void mma_f16(float* d, const uint32_t* a, uint32_t b0, uint32_t b1) {
    asm volatile(
        "mma.sync.aligned.m16n8k16.row.col.f32.f16.f16.f32 "
        "{%0,%1,%2,%3}, {%4,%5,%6,%7}, {%8,%9}, {%0,%1,%2,%3};"
        : "+f"(d[0]), "+f"(d[1]), "+f"(d[2]), "+f"(d[3])
        : "r"(a[0]), "r"(a[1]), "r"(a[2]), "r"(a[3]), "r"(b0), "r"(b1));
}
__device__ __forceinline__ void bar_pair(int id) {
    asm volatile("bar.sync %0, 64;" :: "r"(id) : "memory");
}

// ---------------------------------------------------------------------------
__global__ void tab_kernel(const int* __restrict__ pos) {
    int idx = blockIdx.x * blockDim.x + threadIdx.x;   // SS*64
    int i = idx & 63, s = idx >> 6;
    float inv = exp2f(-(float)i * (L2K / 64.f));
    float sn, cs;
    sincosf((float)pos[s] * inv, &sn, &cs);
    g_cs[idx] = cs;
    g_sn[idx] = sn;
}

__global__ void rope_k_kernel(const float* __restrict__ k) {
    int idx = blockIdx.x * blockDim.x + threadIdx.x;   // SS*KVHN*64
    int i = idx & 63;
    int kv = (idx >> 6) & 7;
    int s = idx >> 9;
    float cs = g_cs[s * 64 + i], sn = g_sn[s * 64 + i];
    const float* kp = k + ((size_t)s * KVHN + kv) * DD;
    float x1 = kp[i], x2 = kp[i + 64];
    __half* op = g_kr + ((size_t)s * KVHN + kv) * DD;
    op[i]      = __float2half_rn(x1 * cs - x2 * sn);
    op[i + 64] = __float2half_rn(x2 * cs + x1 * sn);
}

__global__ void vr_kernel(const float* __restrict__ v) {
    int idx = blockIdx.x * blockDim.x + threadIdx.x;   // SS*KVHN*DD
    g_vr[idx] = __float2half_rn(v[idx]);
}

// ---------------------------------------------------------------------------
extern __shared__ __half smh[];

__global__ __launch_bounds__(512, 1) void attn_kernel(
    const float* __restrict__ q,
    const int* __restrict__ pos,
    const float* __restrict__ sinks,
    float* __restrict__ out)
{
    __half* Qs = smh + QS_OFF;
    __half* Ps = smh + PS_OFF;
    float*  Den = (float*)(smh + DEN_OFF);   // [2][128]

    int tid = threadIdx.x;
    int wid = tid >> 5, lane = tid & 31;
    int qg = wid >> 1, dh = wid & 1;         // warp = (q-group, d/key half)
    int lq = lane >> 2;
    int lr = lane & 3;
    int qt = blockIdx.x, h = blockIdx.y;
    int q0 = qt * BM, kvh = h >> 2;
    int w16 = qg * 16;

    uint32_t qs_b = smem_u32(Qs), ps_b = smem_u32(Ps);
    uint32_t ks_b[2] = { smem_u32(smh + KS0_OFF), smem_u32(smh + KS1_OFF) };
    uint32_t vs_b[2] = { smem_u32(smh + VS0_OFF), smem_u32(smh + VS1_OFF) };
    uint32_t pk_b[2] = { smem_u32(smh + PK0_OFF), smem_u32(smh + PK1_OFF) };
    const int* PK0 = (const int*)(smh + PK0_OFF);
    const int* PK1 = (const int*)(smh + PK1_OFF);

    // per-lane ldmatrix address components
    int l15 = lane & 15, lh = (lane >> 4) & 1;
    int l7 = lane & 7, l8 = (lane >> 3) & 1;
    uint32_t qa_base = qs_b + (uint32_t)(((w16 + l15) * STRQ + lh * 8) * 2);
    uint32_t pa_base = ps_b + (uint32_t)(((w16 + l15) * STRP + lh * 8) * 2);
    // QK B: key rows dh*32 + nbp*16 + (l7 + lh*8), dim cols l8*8 + ks*16
    uint32_t ka_off = (uint32_t)(((dh * 32 + l7 + lh * 8) * STRQ + l8 * 8) * 2);
    // PV B (trans): key rows ks*16 + (l7 + l8*8), dim cols dh*64 + nbp*16 + lh*8
    uint32_t va_off = (uint32_t)(((l7 + l8 * 8) * STRQ + dh * 64 + lh * 8) * 2);

    // cp.async prefetch slots (2 x 16B chunks each for K and V; 1024 chunks total)
    int pf_row[2], pf_c[2];
    #pragma unroll
    for (int j = 0; j < 2; j++) {
        int f = tid + 512 * j;
        pf_row[j] = f >> 4;
        pf_c[j] = f & 15;
    }

    // ---- Q prologue: RoPE + scale -> fp16 Qs ----
    {
        int row = tid >> 2, g = tid & 3;
        int qg2 = q0 + row;
        const float* qr = q + ((size_t)qg2 * HH + h) * DD;
        #pragma unroll
        for (int ii = 0; ii < 16; ii++) {
            int r = g * 16 + ii;
            float cs = g_cs[qg2 * 64 + r], sn = g_sn[qg2 * 64 + r];
            float x1 = qr[r], x2 = qr[r + 64];
            Qs[row * STRQ + r]      = __float2half_rn(SCALE_F * (x1 * cs - x2 * sn));
            Qs[row * STRQ + r + 64] = __float2half_rn(SCALE_F * (x2 * cs + x1 * sn));
        }
    }

    int pq0 = pos[q0 + w16 + lq];
    int pq1 = pos[q0 + w16 + lq + 8];
    float den0 = 0.f, den1 = 0.f;

    float ofr[8][4];
    #pragma unroll
    for (int i = 0; i < 8; i++)
        #pragma unroll
        for (int j = 0; j < 4; j++) ofr[i][j] = 0.f;

    int kstart = q0 - (WIN - 1);
    if (kstart < 0) kstart = 0;
    kstart &= ~(BN - 1);
    int nt = (q0 + BM - kstart) / BN;

    // ---- prefetch tile 0 into buffer 0 ----
    {
        int kb = kstart;
        #pragma unroll
        for (int j = 0; j < 2; j++) {
            const size_t gb = ((size_t)(kb + pf_row[j]) * KVHN + kvh) * DD + pf_c[j] * 8;
            uint32_t so = (uint32_t)((pf_row[j] * STRQ + pf_c[j] * 8) * 2);
            cp16(ks_b[0] + so, g_kr + gb);
            cp16(vs_b[0] + so, g_vr + gb);
        }
        if (tid < 16) cp16(pk_b[0] + tid * 16, (const char*)(pos + kb) + tid * 16);
        cp_commit();
    }

    for (int it = 0; it < nt; it++) {
        int b = it & 1;
        cp_wait0();
        __syncthreads();     // tile `it` published; prev reads of buf b done

        // ---- prefetch tile it+1 into the other buffer ----
        if (it + 1 < nt) {
            int kb = kstart + (it + 1) * BN;
            #pragma unroll
            for (int j = 0; j < 2; j++) {
                const size_t gb = ((size_t)(kb + pf_row[j]) * KVHN + kvh) * DD + pf_c[j] * 8;
                uint32_t so = (uint32_t)((pf_row[j] * STRQ + pf_c[j] * 8) * 2);
                cp16(ks_b[b ^ 1] + so, g_kr + gb);
                cp16(vs_b[b ^ 1] + so, g_vr + gb);
            }
            if (tid < 16) cp16(pk_b[b ^ 1] + tid * 16, (const char*)(pos + kb) + tid * 16);
            cp_commit();
        }

        uint32_t ka_base = ks_b[b] + ka_off;
        uint32_t va_base = vs_b[b] + va_off;
        const int* PKs = b ? PK1 : PK0;

        // ---- QK: s[16 x 32] per warp (keys dh*32..dh*32+32) ----
        float sfr[4][4];
        #pragma unroll
        for (int i = 0; i < 4; i++)
            #pragma unroll
            for (int j = 0; j < 4; j++) sfr[i][j] = 0.f;

        #pragma unroll
        for (int ks = 0; ks < 8; ks++) {
            uint32_t a[4];
            ldm_x4(a, qa_base + ks * 32);
            #pragma unroll
            for (int nbp = 0; nbp < 2; nbp++) {
                uint32_t bfr[4];
                ldm_x4(bfr, ka_base + (uint32_t)((nbp * 16 * STRQ) * 2) + ks * 32);
                mma_f16(sfr[2 * nbp],     a, bfr[0], bfr[1]);
                mma_f16(sfr[2 * nbp + 1], a, bfr[2], bfr[3]);
            }
        }

        // ---- softmax: p = exp(s - CFIX), masked; fp16 P -> Ps cols dh*32.. ----
        #pragma unroll
        for (int nb = 0; nb < 4; nb++) {
            int c0 = dh * 32 + nb * 8 + 2 * lr;
            int pk0 = PKs[c0], pk1 = PKs[c0 + 1];
            float p0 = (pk0 <= pq0 && pq0 - pk0 < WIN) ? __expf(sfr[nb][0] - CFIX) : 0.f;
            float p1 = (pk1 <= pq0 && pq0 - pk1 < WIN) ? __expf(sfr[nb][1] - CFIX) : 0.f;
            float p2 = (pk0 <= pq1 && pq1 - pk0 < WIN) ? __expf(sfr[nb][2] - CFIX) : 0.f;
            float p3 = (pk1 <= pq1 && pq1 - pk1 < WIN) ? __expf(sfr[nb][3] - CFIX) : 0.f;
            den0 += p0 + p1;
            den1 += p2 + p3;
            *(__half2*)&Ps[(w16 + lq) * STRP + c0]     = __floats2half2_rn(p0, p1);
            *(__half2*)&Ps[(w16 + lq + 8) * STRP + c0] = __floats2half2_rn(p2, p3);
        }
        bar_pair(1 + qg);   // both halves of P rows published within warp pair

        // ---- PV: o[16 x 64] += P[16x64] x V[64 x 64] (cols dh*64..) ----
        #pragma unroll
        for (int ks = 0; ks < 4; ks++) {
            uint32_t a[4];
            ldm_x4(a, pa_base + ks * 32);
            #pragma unroll
            for (int nbp = 0; nbp < 4; nbp++) {
                uint32_t bfr[4];
                ldm_x4_t(bfr, va_base + (uint32_t)((ks * 16 * STRQ + nbp * 16) * 2));
                mma_f16(ofr[2 * nbp],     a, bfr[0], bfr[1]);
                mma_f16(ofr[2 * nbp + 1], a, bfr[2], bfr[3]);
            }
        }
        __syncthreads();   // all warps done with buf b + P before refill/rewrite
    }

    // ---- epilogue: combine partial denominators across warp pairs ----
    den0 += __shfl_xor_sync(0xffffffffu, den0, 1);
    den0 += __shfl_xor_sync(0xffffffffu, den0, 2);
    den1 += __shfl_xor_sync(0xffffffffu, den1, 1);
    den1 += __shfl_xor_sync(0xffffffffu, den1, 2);
    if (lr == 0) {
        Den[dh * 128 + w16 + lq] = den0;
        Den[dh * 128 + w16 + lq + 8] = den1;
    }
    __syncthreads();
    float sk = __expf(sinks[h] - CFIX);
    float inv0 = 1.0f / (Den[w16 + lq] + Den[128 + w16 + lq] + sk);
    float inv1 = 1.0f / (Den[w16 + lq + 8] + Den[128 + w16 + lq + 8] + sk);

    int row0 = q0 + w16 + lq;
    int row1 = row0 + 8;
    float* op0 = out + ((size_t)row0 * HH + h) * DD + dh * 64;
    float* op1 = out + ((size_t)row1 * HH + h) * DD + dh * 64;
    #pragma unroll
    for (int nb = 0; nb < 8; nb++) {
        int c = nb * 8 + 2 * lr;
        *(float2*)(op0 + c) = make_float2(ofr[nb][0] * inv0, ofr[nb][1] * inv0);
        *(float2*)(op1 + c) = make_float2(ofr[nb][2] * inv1, ofr[nb][3] * inv1);
    }
}

// ---------------------------------------------------------------------------
extern "C" void kernel_launch(void* const* d_in, const int* in_sizes, int n_in,
                              void* d_out, int out_size) {
    (void)in_sizes; (void)n_in; (void)out_size;
    const float* q     = (const float*)d_in[0];
    const float* k     = (const float*)d_in[1];
    const float* v     = (const float*)d_in[2];
    const int*   pos   = (const int*)d_in[3];
    const float* sinks = (const float*)d_in[4];
    float* out = (float*)d_out;

    tab_kernel<<<(SS * 64) / 256, 256>>>(pos);
    rope_k_kernel<<<(SS * KVHN * 64) / 256, 256>>>(k);
    vr_kernel<<<(SS * KVHN * DD) / 256, 256>>>(v);

    size_t smem = SMEM_HALVES * sizeof(__half);
    cudaFuncSetAttribute(attn_kernel, cudaFuncAttributeMaxDynamicSharedMemorySize, (int)smem);
    dim3 grid(SS / BM, HH);
    attn_kernel<<<grid, 512, smem>>>(q, pos, sinks, out);
}